// round 7
// baseline (speedup 1.0000x reference)
#include <cuda_runtime.h>
#include <cuda_fp16.h>
#include <cstdint>

// sigma = rsqrt( exp(-||z-c_k||^2 * lam_k) @ (W*W) + eps )
// B=262144, K=64, DZ=128, OUT=16.
// f16-split mma.sync.m16n8k16 + ldmatrix + conflict-free staggered staging.

constexpr int K    = 64;
constexpr int DZ   = 128;
constexpr int OUTD = 16;
constexpr int MT   = 128;    // rows per CTA
constexpr int NTHR = 256;    // 8 warps
constexpr float EPS = 1e-6f;

constexpr int SA = 136;      // f16 stride (68 words ≡ 4 mod 8: ldmatrix conflict-free)
constexpr int SB = 136;
constexpr int SV = 72;       // 36 words ≡ 4 mod 8
constexpr int SW = 72;

constexpr int OFF_AH  = 0;                         // [128][136] f16
constexpr int OFF_AL  = OFF_AH + MT * SA * 2;      // 34816
constexpr int OFF_BH  = OFF_AL + MT * SA * 2;      // 69632  [64][136]
constexpr int OFF_BL  = OFF_BH + K * SB * 2;       // 87040
constexpr int OFF_WH  = OFF_BL + K * SB * 2;       // 104448 [16][72]
constexpr int OFF_WL  = OFF_WH + OUTD * SW * 2;    // 106752
constexpr int OFF_LAM = OFF_WL + OUTD * SW * 2;    // 109056
constexpr int OFF_C2  = OFF_LAM + 256;
constexpr int OFF_Z2  = OFF_C2 + 256;
constexpr int SMEM_BYTES = OFF_Z2 + 512;           // 110080
constexpr int OFF_VH  = OFF_AH;                    // V overlays A after GEMM1

__device__ __forceinline__ uint32_t smem_u32(const void* p) {
    uint32_t a;
    asm("{ .reg .u64 t; cvta.to.shared.u64 t, %1; cvt.u32.u64 %0, t; }" : "=r"(a) : "l"(p));
    return a;
}
__device__ __forceinline__ void ldsm4(uint32_t* r, uint32_t a) {
    asm volatile("ldmatrix.sync.aligned.m8n8.x4.shared.b16 {%0,%1,%2,%3}, [%4];"
                 : "=r"(r[0]), "=r"(r[1]), "=r"(r[2]), "=r"(r[3]) : "r"(a));
}
__device__ __forceinline__ void mma16816(float* c, const uint32_t* a,
                                         uint32_t b0, uint32_t b1) {
    asm volatile(
        "mma.sync.aligned.m16n8k16.row.col.f32.f16.f16.f32 "
        "{%0,%1,%2,%3}, {%4,%5,%6,%7}, {%8,%9}, {%0,%1,%2,%3};"
        : "+f"(c[0]), "+f"(c[1]), "+f"(c[2]), "+f"(c[3])
        : "r"(a[0]), "r"(a[1]), "r"(a[2]), "r"(a[3]), "r"(b0), "r"(b1));
}
__device__ __forceinline__ uint32_t split_pack2(float f0, float f1, uint32_t& lo_pack) {
    __half h0 = __float2half_rn(f0);
    __half h1 = __float2half_rn(f1);
    __half l0 = __float2half_rn(f0 - __half2float(h0));
    __half l1 = __float2half_rn(f1 - __half2float(h1));
    lo_pack = (uint32_t)__half_as_ushort(l0) | ((uint32_t)__half_as_ushort(l1) << 16);
    return (uint32_t)__half_as_ushort(h0) | ((uint32_t)__half_as_ushort(h1) << 16);
}

__global__ __launch_bounds__(NTHR, 2)
void varnet_hmma(const float* __restrict__ z,
                 const float* __restrict__ cnts,
                 const float* __restrict__ lams,
                 const float* __restrict__ W,
                 float* __restrict__ out,
                 int B)
{
    extern __shared__ __align__(16) char smem[];
    const uint32_t sb = smem_u32(smem);
    float* s_lam = reinterpret_cast<float*>(smem + OFF_LAM);
    float* s_c2  = reinterpret_cast<float*>(smem + OFF_C2);
    float* s_z2  = reinterpret_cast<float*>(smem + OFF_Z2);

    const int t    = threadIdx.x;
    const int wid  = t >> 5;
    const int lane = t & 31;
    const int gid  = lane >> 2;
    const int tig  = lane & 3;
    const int row0 = blockIdx.x * MT;

    // ========== staging: z, staggered conflict-free STS.64 ==========
    {
        const int r  = t >> 1;                 // row within tile
        const int h  = t & 1;                  // k-half
        const int kh = h * 64;
        const long long grow = (long long)row0 + r;
        const float* zr = z + grow * DZ;
        float z2p = 0.f;
        #pragma unroll
        for (int i = 0; i < 16; i++) {
            const int j = (i + r + 8 * h) & 15;       // 4-f16 chunk within half
            const int d = kh + 4 * j;
            float4 v = (grow < B)
                ? *reinterpret_cast<const float4*>(zr + d)
                : make_float4(0.f, 0.f, 0.f, 0.f);
            z2p = fmaf(v.x, v.x, fmaf(v.y, v.y, fmaf(v.z, v.z, fmaf(v.w, v.w, z2p))));
            uint32_t l0, l1;
            uint32_t h0 = split_pack2(v.x, v.y, l0);
            uint32_t h1 = split_pack2(v.z, v.w, l1);
            const int byo = (r * SA + d) * 2;
            *reinterpret_cast<uint64_t*>(smem + OFF_AH + byo) =
                (uint64_t)h0 | ((uint64_t)h1 << 32);
            *reinterpret_cast<uint64_t*>(smem + OFF_AL + byo) =
                (uint64_t)l0 | ((uint64_t)l1 << 32);
        }
        z2p += __shfl_xor_sync(0xFFFFFFFFu, z2p, 1);
        if (h == 0) s_z2[r] = z2p;
    }

    // ========== staging: 2*cnts (t<128) / W^2 + lam (t>=128) ==========
    if (t < 128) {
        const int r  = t >> 1;                 // center 0..63
        const int h  = t & 1;
        const int kh = h * 64;
        const float* cr = cnts + r * DZ;
        float c2p = 0.f;
        #pragma unroll
        for (int i = 0; i < 16; i++) {
            const int j = (i + r + 8 * h) & 15;
            const int d = kh + 4 * j;
            float4 v = *reinterpret_cast<const float4*>(cr + d);
            c2p = fmaf(v.x, v.x, fmaf(v.y, v.y, fmaf(v.z, v.z, fmaf(v.w, v.w, c2p))));
            uint32_t l0, l1;
            uint32_t h0 = split_pack2(2.f * v.x, 2.f * v.y, l0);
            uint32_t h1 = split_pack2(2.f * v.z, 2.f * v.w, l1);
            const int byo = (r * SB + d) * 2;
            *reinterpret_cast<uint64_t*>(smem + OFF_BH + byo) =
                (uint64_t)h0 | ((uint64_t)h1 << 32);
            *reinterpret_cast<uint64_t*>(smem + OFF_BL + byo) =
                (uint64_t)l0 | ((uint64_t)l1 << 32);
        }
        c2p += __shfl_xor_sync(0xFFFFFFFFu, c2p, 1);
        if (h == 0) s_c2[r] = c2p;
    } else {
        const int tt = t - 128;
        #pragma unroll
        for (int i = 0; i < 8; i++) {
            const int idx = tt * 8 + i;        // W is [64][16] row-major
            const int kc = idx >> 4, j = idx & 15;
            float w = W[idx];
            float w2 = w * w;
            __half hh = __float2half_rn(w2);
            __half hl = __float2half_rn(w2 - __half2float(hh));
            const int byo = (j * SW + kc) * 2;
            *reinterpret_cast<uint16_t*>(smem + OFF_WH + byo) = __half_as_ushort(hh);
            *reinterpret_cast<uint16_t*>(smem + OFF_WL + byo) = __half_as_ushort(hl);
        }
        if (tt < K) s_lam[tt] = lams[tt];
    }
    __syncthreads();

    // ========== GEMM1: dot[128x64] = z . (2c)^T via ldmatrix + HMMA ==========
    float acc[8][4];
    #pragma unroll
    for (int nt = 0; nt < 8; nt++)
        #pragma unroll
        for (int q = 0; q < 4; q++) acc[nt][q] = 0.f;

    // per-lane ldmatrix base addresses
    const uint32_t aA = sb + OFF_AH +
        (uint32_t)(((16 * wid + (lane & 15)) * SA + 8 * ((lane >> 4) & 1)) * 2);
    const uint32_t aAl = aA + (OFF_AL - OFF_AH);
    const uint32_t laneB =
        (uint32_t)((((lane & 7) + 8 * ((lane >> 4) & 1)) * SB + 8 * ((lane >> 3) & 1)) * 2);
    const uint32_t aB  = sb + OFF_BH + laneB;
    const uint32_t aBl = sb + OFF_BL + laneB;

    #pragma unroll
    for (int s = 0; s < 8; s++) {
        const uint32_t ks = (uint32_t)(32 * s);
        uint32_t ah[4], al[4];
        ldsm4(ah, aA  + ks);
        ldsm4(al, aAl + ks);
        #pragma unroll
        for (int p = 0; p < 4; p++) {               // nt pair (2p, 2p+1)
            const uint32_t po = (uint32_t)(p * 16 * SB * 2) + ks;
            uint32_t bh[4], bl[4];
            ldsm4(bh, aB  + po);
            ldsm4(bl, aBl + po);
            mma16816(acc[2 * p],     ah, bh[0], bh[1]);
            mma16816(acc[2 * p],     ah, bl[0], bl[1]);
            mma16816(acc[2 * p],     al, bh[0], bh[1]);
            mma16816(acc[2 * p + 1], ah, bh[2], bh[3]);
            mma16816(acc[2 * p + 1], ah, bl[2], bl[3]);
            mma16816(acc[2 * p + 1], al, bh[2], bh[3]);
        }
    }

    // ===== epilogue 1: V = exp(-lam*(z2+c2-dot)) (regs), then store f16 hi =====
    uint32_t vpack[8][2];
    {
        const int rA0 = 16 * wid + gid;
        const float z20 = s_z2[rA0];
        const float z21 = s_z2[rA0 + 8];
        #pragma unroll
        for (int nt = 0; nt < 8; nt++) {
            const int n0 = nt * 8 + tig * 2;
            const float c20 = s_c2[n0], c21 = s_c2[n0 + 1];
            const float lm0 = s_lam[n0], lm1 = s_lam[n0 + 1];
            float v00 = __expf(-lm0 * (z20 + c20 - acc[nt][0]));
            float v01 = __expf(-lm1 * (z20 + c21 - acc[nt][1]));
            float v10 = __expf(-lm0 * (z21 + c20 - acc[nt][2]));
            float v11 = __expf(-lm1 * (z21 + c21 - acc[nt][3]));
            __half a0 = __float2half_rn(v00), a1 = __float2half_rn(v01);
            __half b0 = __float2half_rn(v10), b1 = __float2half_rn(v11);
            vpack[nt][0] = (uint32_t)__half_as_ushort(a0) |
                           ((uint32_t)__half_as_ushort(a1) << 16);
            vpack[nt][1] = (uint32_t)__half_as_ushort(b0) |
                           ((uint32_t)__half_as_ushort(b1) << 16);
        }
    }
    __syncthreads();   // all GEMM1 reads of A region done before V overlay
    {
        const int rA0 = 16 * wid + gid;
        #pragma unroll
        for (int nt = 0; nt < 8; nt++) {
            const int n0 = nt * 8 + tig * 2;
            *reinterpret_cast<uint32_t*>(smem + OFF_VH + (rA0 * SV + n0) * 2)       = vpack[nt][0];
            *reinterpret_cast<uint32_t*>(smem + OFF_VH + ((rA0 + 8) * SV + n0) * 2) = vpack[nt][1];
        }
    }
    __syncwarp();      // V rows are warp-private: warp-level visibility suffices

    // ========== GEMM2: beta[128x16] = Vh @ (W2h + W2l), K=64 ==========
    float acc2[2][4];
    #pragma unroll
    for (int nt = 0; nt < 2; nt++)
        #pragma unroll
        for (int q = 0; q < 4; q++) acc2[nt][q] = 0.f;
    {
        const uint32_t aV = sb + OFF_VH +
            (uint32_t)(((16 * wid + (lane & 15)) * SV + 8 * ((lane >> 4) & 1)) * 2);
        const uint32_t laneW =
            (uint32_t)((((lane & 7) + 8 * ((lane >> 4) & 1)) * SW + 8 * ((lane >> 3) & 1)) * 2);
        const uint32_t aW  = sb + OFF_WH + laneW;
        const uint32_t aWl = sb + OFF_WL + laneW;

        #pragma unroll
        for (int s = 0; s < 4; s++) {
            const uint32_t ks = (uint32_t)(32 * s);
            uint32_t vh[4], wh[4], wl[4];
            ldsm4(vh, aV  + ks);
            ldsm4(wh, aW  + ks);
            ldsm4(wl, aWl + ks);
            mma16816(acc2[0], vh, wh[0], wh[1]);
            mma16816(acc2[0], vh, wl[0], wl[1]);
            mma16816(acc2[1], vh, wh[2], wh[3]);
            mma16816(acc2[1], vh, wl[2], wl[3]);
        }
    }

    // ========== epilogue 2: sigma = rsqrt(beta+eps), store ==========
    {
        const int r0 = 16 * wid + gid;
        const long long g0 = (long long)row0 + r0;
        const long long g1 = g0 + 8;
        #pragma unroll
        for (int nt = 0; nt < 2; nt++) {
            const int j0 = nt * 8 + tig * 2;
            if (g0 < B) {
                float2 o = make_float2(rsqrtf(acc2[nt][0] + EPS),
                                       rsqrtf(acc2[nt][1] + EPS));
                *reinterpret_cast<float2*>(out + g0 * OUTD + j0) = o;
            }
            if (g1 < B) {
                float2 o = make_float2(rsqrtf(acc2[nt][2] + EPS),
                                       rsqrtf(acc2[nt][3] + EPS));
                *reinterpret_cast<float2*>(out + g1 * OUTD + j0) = o;
            }
        }
    }
}

extern "C" void kernel_launch(void* const* d_in, const int* in_sizes, int n_in,
                              void* d_out, int out_size)
{
    const float* z    = (const float*)d_in[0];
    const float* cnts = (const float*)d_in[1];
    const float* lams = (const float*)d_in[2];
    const float* W    = (const float*)d_in[3];
    float* out = (float*)d_out;

    const int B = in_sizes[0] / DZ;
    cudaFuncSetAttribute(varnet_hmma,
                         cudaFuncAttributeMaxDynamicSharedMemorySize, SMEM_BYTES);
    const int grid = (B + MT - 1) / MT;
    varnet_hmma<<<grid, NTHR, SMEM_BYTES>>>(z, cnts, lams, W, out, B);
}

// round 9
// speedup vs baseline: 1.0024x; 1.0024x over previous
#include <cuda_runtime.h>
#include <cuda_fp16.h>
#include <cstdint>

// sigma = rsqrt( exp(-||z-c_k||^2 * lam_k) @ (W*W) + eps )
// B=262144, K=64, DZ=128, OUT=16.
// f16-split mma.sync.m16n8k16 + ldmatrix, software-pipelined fragment loads.

constexpr int K    = 64;
constexpr int DZ   = 128;
constexpr int OUTD = 16;
constexpr int MT   = 128;    // rows per CTA
constexpr int NTHR = 256;    // 8 warps
constexpr float EPS = 1e-6f;

constexpr int SA = 136;      // f16 stride (68 words ≡ 4 mod 8: ldmatrix conflict-free)
constexpr int SB = 136;
constexpr int SV = 72;
constexpr int SW = 72;

constexpr int OFF_AH  = 0;                         // [128][136] f16
constexpr int OFF_AL  = OFF_AH + MT * SA * 2;      // 34816
constexpr int OFF_BH  = OFF_AL + MT * SA * 2;      // 69632  [64][136]
constexpr int OFF_BL  = OFF_BH + K * SB * 2;       // 87040
constexpr int OFF_WH  = OFF_BL + K * SB * 2;       // 104448 [16][72]
constexpr int OFF_WL  = OFF_WH + OUTD * SW * 2;    // 106752
constexpr int OFF_LAM = OFF_WL + OUTD * SW * 2;    // 109056
constexpr int OFF_C2  = OFF_LAM + 256;
constexpr int OFF_Z2  = OFF_C2 + 256;
constexpr int SMEM_BYTES = OFF_Z2 + 512;           // 110080
constexpr int OFF_VH  = OFF_AH;                    // V overlays A after GEMM1

__device__ __forceinline__ uint32_t smem_u32(const void* p) {
    uint32_t a;
    asm("{ .reg .u64 t; cvta.to.shared.u64 t, %1; cvt.u32.u64 %0, t; }" : "=r"(a) : "l"(p));
    return a;
}
__device__ __forceinline__ void ldsm4(uint32_t* r, uint32_t a) {
    asm volatile("ldmatrix.sync.aligned.m8n8.x4.shared.b16 {%0,%1,%2,%3}, [%4];"
                 : "=r"(r[0]), "=r"(r[1]), "=r"(r[2]), "=r"(r[3]) : "r"(a));
}
__device__ __forceinline__ void mma16816(float* c, const uint32_t* a,
                                         uint32_t b0, uint32_t b1) {
    asm volatile(
        "mma.sync.aligned.m16n8k16.row.col.f32.f16.f16.f32 "
        "{%0,%1,%2,%3}, {%4,%5,%6,%7}, {%8,%9}, {%0,%1,%2,%3};"
        : "+f"(c[0]), "+f"(c[1]), "+f"(c[2]), "+f"(c[3])
        : "r"(a[0]), "r"(a[1]), "r"(a[2]), "r"(a[3]), "r"(b0), "r"(b1));
}
__device__ __forceinline__ uint32_t split_pack2(float f0, float f1, uint32_t& lo_pack) {
    __half h0 = __float2half_rn(f0);
    __half h1 = __float2half_rn(f1);
    __half l0 = __float2half_rn(f0 - __half2float(h0));
    __half l1 = __float2half_rn(f1 - __half2float(h1));
    lo_pack = (uint32_t)__half_as_ushort(l0) | ((uint32_t)__half_as_ushort(l1) << 16);
    return (uint32_t)__half_as_ushort(h0) | ((uint32_t)__half_as_ushort(h1) << 16);
}

__global__ __launch_bounds__(NTHR, 2)
void varnet_hmma(const float* __restrict__ z,
                 const float* __restrict__ cnts,
                 const float* __restrict__ lams,
                 const float* __restrict__ W,
                 float* __restrict__ out,
                 int B)
{
    extern __shared__ __align__(16) char smem[];
    const uint32_t sb = smem_u32(smem);
    float* s_lam = reinterpret_cast<float*>(smem + OFF_LAM);
    float* s_c2  = reinterpret_cast<float*>(smem + OFF_C2);
    float* s_z2  = reinterpret_cast<float*>(smem + OFF_Z2);

    const int t    = threadIdx.x;
    const int wid  = t >> 5;
    const int lane = t & 31;
    const int gid  = lane >> 2;
    const int tig  = lane & 3;
    const int row0 = blockIdx.x * MT;

    // ========== staging: z, staggered conflict-free STS.64 ==========
    {
        const int r  = t >> 1;
        const int h  = t & 1;
        const int kh = h * 64;
        const long long grow = (long long)row0 + r;
        const float* zr = z + grow * DZ;
        float z2p = 0.f;
        #pragma unroll
        for (int i = 0; i < 16; i++) {
            const int j = (i + r + 8 * h) & 15;
            const int d = kh + 4 * j;
            float4 v = (grow < B)
                ? *reinterpret_cast<const float4*>(zr + d)
                : make_float4(0.f, 0.f, 0.f, 0.f);
            z2p = fmaf(v.x, v.x, fmaf(v.y, v.y, fmaf(v.z, v.z, fmaf(v.w, v.w, z2p))));
            uint32_t l0, l1;
            uint32_t h0 = split_pack2(v.x, v.y, l0);
            uint32_t h1 = split_pack2(v.z, v.w, l1);
            const int byo = (r * SA + d) * 2;
            *reinterpret_cast<uint64_t*>(smem + OFF_AH + byo) =
                (uint64_t)h0 | ((uint64_t)h1 << 32);
            *reinterpret_cast<uint64_t*>(smem + OFF_AL + byo) =
                (uint64_t)l0 | ((uint64_t)l1 << 32);
        }
        z2p += __shfl_xor_sync(0xFFFFFFFFu, z2p, 1);
        if (h == 0) s_z2[r] = z2p;
    }

    // ========== staging: 2*cnts (t<128) / W^2 + lam (t>=128) ==========
    if (t < 128) {
        const int r  = t >> 1;
        const int h  = t & 1;
        const int kh = h * 64;
        const float* cr = cnts + r * DZ;
        float c2p = 0.f;
        #pragma unroll
        for (int i = 0; i < 16; i++) {
            const int j = (i + r + 8 * h) & 15;
            const int d = kh + 4 * j;
            float4 v = *reinterpret_cast<const float4*>(cr + d);
            c2p = fmaf(v.x, v.x, fmaf(v.y, v.y, fmaf(v.z, v.z, fmaf(v.w, v.w, c2p))));
            uint32_t l0, l1;
            uint32_t h0 = split_pack2(2.f * v.x, 2.f * v.y, l0);
            uint32_t h1 = split_pack2(2.f * v.z, 2.f * v.w, l1);
            const int byo = (r * SB + d) * 2;
            *reinterpret_cast<uint64_t*>(smem + OFF_BH + byo) =
                (uint64_t)h0 | ((uint64_t)h1 << 32);
            *reinterpret_cast<uint64_t*>(smem + OFF_BL + byo) =
                (uint64_t)l0 | ((uint64_t)l1 << 32);
        }
        c2p += __shfl_xor_sync(0xFFFFFFFFu, c2p, 1);
        if (h == 0) s_c2[r] = c2p;
    } else {
        const int tt = t - 128;
        #pragma unroll
        for (int i = 0; i < 8; i++) {
            const int idx = tt * 8 + i;        // W is [64][16] row-major
            const int kc = idx >> 4, j = idx & 15;
            float w = W[idx];
            float w2 = w * w;
            __half hh = __float2half_rn(w2);
            __half hl = __float2half_rn(w2 - __half2float(hh));
            const int byo = (j * SW + kc) * 2;
            *reinterpret_cast<uint16_t*>(smem + OFF_WH + byo) = __half_as_ushort(hh);
            *reinterpret_cast<uint16_t*>(smem + OFF_WL + byo) = __half_as_ushort(hl);
        }
        if (tt < K) s_lam[tt] = lams[tt];
    }
    __syncthreads();

    // ===== GEMM1: dot[128x64] = z.(2c)^T, software-pipelined ldsm/HMMA =====
    float acc[8][4];
    #pragma unroll
    for (int nt = 0; nt < 8; nt++)
        #pragma unroll
        for (int q = 0; q < 4; q++) acc[nt][q] = 0.f;

    const uint32_t aA = sb + OFF_AH +
        (uint32_t)(((16 * wid + (lane & 15)) * SA + 8 * ((lane >> 4) & 1)) * 2);
    const uint32_t aAl = aA + (OFF_AL - OFF_AH);
    const uint32_t laneB =
        (uint32_t)((((lane & 7) + 8 * ((lane >> 4) & 1)) * SB + 8 * ((lane >> 3) & 1)) * 2);
    const uint32_t aB  = sb + OFF_BH + laneB;
    const uint32_t aBl = sb + OFF_BL + laneB;
    constexpr uint32_t BP = (uint32_t)(16 * SB * 2);   // n-tile-pair stride

    {
        uint32_t ah[2][4], al[2][4], bh[2][4], bl[2][4];
        // prologue: s=0 A frags, (s=0,p=0) B frags
        ldsm4(ah[0], aA);
        ldsm4(al[0], aAl);
        ldsm4(bh[0], aB);
        ldsm4(bl[0], aBl);

        #pragma unroll
        for (int it = 0; it < 32; it++) {
            const int s  = it >> 2;
            const int p  = it & 3;
            const int sa = s & 1;          // A buffer for this s
            const int bb = it & 1;         // B buffer for this it
            // prefetch next iteration's fragments before consuming current
            if (it + 1 < 32) {
                const int ns = (it + 1) >> 2;
                const int np = (it + 1) & 3;
                const uint32_t nks = (uint32_t)(32 * ns);
                if (np == 0) {
                    ldsm4(ah[ns & 1], aA  + nks);
                    ldsm4(al[ns & 1], aAl + nks);
                }
                ldsm4(bh[1 - bb], aB  + (uint32_t)np * BP + nks);
                ldsm4(bl[1 - bb], aBl + (uint32_t)np * BP + nks);
            }
            float* c0 = acc[2 * p];
            float* c1 = acc[2 * p + 1];
            mma16816(c0, ah[sa], bh[bb][0], bh[bb][1]);
            mma16816(c0, ah[sa], bl[bb][0], bl[bb][1]);
            mma16816(c0, al[sa], bh[bb][0], bh[bb][1]);
            mma16816(c1, ah[sa], bh[bb][2], bh[bb][3]);
            mma16816(c1, ah[sa], bl[bb][2], bl[bb][3]);
            mma16816(c1, al[sa], bh[bb][2], bh[bb][3]);
        }
    }

    // ===== epilogue 1: V = exp(-lam*(z2+c2-dot)) (regs), then store f16 hi =====
    uint32_t vpack[8][2];
    {
        const int rA0 = 16 * wid + gid;
        const float z20 = s_z2[rA0];
        const float z21 = s_z2[rA0 + 8];
        #pragma unroll
        for (int nt = 0; nt < 8; nt++) {
            const int n0 = nt * 8 + tig * 2;
            const float c20 = s_c2[n0], c21 = s_c2[n0 + 1];
            const float lm0 = s_lam[n0], lm1 = s_lam[n0 + 1];
            float v00 = __expf(-lm0 * (z20 + c20 - acc[nt][0]));
            float v01 = __expf(-lm1 * (z20 + c21 - acc[nt][1]));
            float v10 = __expf(-lm0 * (z21 + c20 - acc[nt][2]));
            float v11 = __expf(-lm1 * (z21 + c21 - acc[nt][3]));
            __half a0 = __float2half_rn(v00), a1 = __float2half_rn(v01);
            __half b0 = __float2half_rn(v10), b1 = __float2half_rn(v11);
            vpack[nt][0] = (uint32_t)__half_as_ushort(a0) |
                           ((uint32_t)__half_as_ushort(a1) << 16);
            vpack[nt][1] = (uint32_t)__half_as_ushort(b0) |
                           ((uint32_t)__half_as_ushort(b1) << 16);
        }
    }
    __syncthreads();   // all GEMM1 reads of A region done before V overlay
    {
        const int rA0 = 16 * wid + gid;
        #pragma unroll
        for (int nt = 0; nt < 8; nt++) {
            const int n0 = nt * 8 + tig * 2;
            *reinterpret_cast<uint32_t*>(smem + OFF_VH + (rA0 * SV + n0) * 2)       = vpack[nt][0];
            *reinterpret_cast<uint32_t*>(smem + OFF_VH + ((rA0 + 8) * SV + n0) * 2) = vpack[nt][1];
        }
    }
    __syncwarp();      // V rows are warp-private

    // ===== GEMM2: beta[128x16] = Vh @ (W2h + W2l), loads hoisted =====
    float acc2[2][4];
    #pragma unroll
    for (int nt = 0; nt < 2; nt++)
        #pragma unroll
        for (int q = 0; q < 4; q++) acc2[nt][q] = 0.f;
    {
        const uint32_t aV = sb + OFF_VH +
            (uint32_t)(((16 * wid + (lane & 15)) * SV + 8 * ((lane >> 4) & 1)) * 2);
        const uint32_t laneW =
            (uint32_t)((((lane & 7) + 8 * ((lane >> 4) & 1)) * SW + 8 * ((lane >> 3) & 1)) * 2);
        const uint32_t aW  = sb + OFF_WH + laneW;
        const uint32_t aWl = sb + OFF_WL + laneW;

        uint32_t vh[4][4], wh[4][4], wl[4][4];
        #pragma unroll
        for (int s = 0; s < 4; s++) {
            const uint32_t ks = (uint32_t)(32 * s);
            ldsm4(vh[s], aV  + ks);
            ldsm4(wh[s], aW  + ks);
            ldsm4(wl[s], aWl + ks);
        }
        #pragma unroll
        for (int s = 0; s < 4; s++) {
            mma16816(acc2[0], vh[s], wh[s][0], wh[s][1]);
            mma16816(acc2[0], vh[s], wl[s][0], wl[s][1]);
            mma16816(acc2[1], vh[s], wh[s][2], wh[s][3]);
            mma16816(acc2[1], vh[s], wl[s][2], wl[s][3]);
        }
    }

    // ========== epilogue 2: sigma = rsqrt(beta+eps), store ==========
    {
        const int r0 = 16 * wid + gid;
        const long long g0 = (long long)row0 + r0;
        const long long g1 = g0 + 8;
        #pragma unroll
        for (int nt = 0; nt < 2; nt++) {
            const int j0 = nt * 8 + tig * 2;
            if (g0 < B) {
                float2 o = make_float2(rsqrtf(acc2[nt][0] + EPS),
                                       rsqrtf(acc2[nt][1] + EPS));
                *reinterpret_cast<float2*>(out + g0 * OUTD + j0) = o;
            }
            if (g1 < B) {
                float2 o = make_float2(rsqrtf(acc2[nt][2] + EPS),
                                       rsqrtf(acc2[nt][3] + EPS));
                *reinterpret_cast<float2*>(out + g1 * OUTD + j0) = o;
            }
        }
    }
}

extern "C" void kernel_launch(void* const* d_in, const int* in_sizes, int n_in,
                              void* d_out, int out_size)
{
    const float* z    = (const float*)d_in[0];
    const float* cnts = (const float*)d_in[1];
    const float* lams = (const float*)d_in[2];
    const float* W    = (const float*)d_in[3];
    float* out = (float*)d_out;

    const int B = in_sizes[0] / DZ;
    cudaFuncSetAttribute(varnet_hmma,
                         cudaFuncAttributeMaxDynamicSharedMemorySize, SMEM_BYTES);
    const int grid = (B + MT - 1) / MT;
    varnet_hmma<<<grid, NTHR, SMEM_BYTES>>>(z, cnts, lams, W, out, B);
}

// round 11
// speedup vs baseline: 1.0629x; 1.0604x over previous
#include <cuda_runtime.h>
#include <cuda_fp16.h>
#include <cstdint>

// sigma = rsqrt( exp(-||z-c_k||^2 * lam_k) @ (W*W) + eps )
// B=262144, K=64, DZ=128, OUT=16.
// f16-split mma.sync.m16n8k16 + ldmatrix; staging uses batched loads (MLP=8)
// and balanced work distribution across all 256 threads.

constexpr int K    = 64;
constexpr int DZ   = 128;
constexpr int OUTD = 16;
constexpr int MT   = 128;    // rows per CTA
constexpr int NTHR = 256;    // 8 warps
constexpr float EPS = 1e-6f;

constexpr int SA = 136;      // f16 stride (68 words = 4 mod 8: ldmatrix conflict-free)
constexpr int SB = 136;
constexpr int SV = 72;
constexpr int SW = 72;

constexpr int OFF_AH  = 0;                         // [128][136] f16
constexpr int OFF_AL  = OFF_AH + MT * SA * 2;      // 34816
constexpr int OFF_BH  = OFF_AL + MT * SA * 2;      // 69632  [64][136]
constexpr int OFF_BL  = OFF_BH + K * SB * 2;       // 87040
constexpr int OFF_WH  = OFF_BL + K * SB * 2;       // 104448 [16][72]
constexpr int OFF_WL  = OFF_WH + OUTD * SW * 2;    // 106752
constexpr int OFF_LAM = OFF_WL + OUTD * SW * 2;    // 109056
constexpr int OFF_C2  = OFF_LAM + 256;
constexpr int OFF_Z2  = OFF_C2 + 256;
constexpr int SMEM_BYTES = OFF_Z2 + 512;           // 110080
constexpr int OFF_VH  = OFF_AH;                    // V overlays A after GEMM1

__device__ __forceinline__ uint32_t smem_u32(const void* p) {
    uint32_t a;
    asm("{ .reg .u64 t; cvta.to.shared.u64 t, %1; cvt.u32.u64 %0, t; }" : "=r"(a) : "l"(p));
    return a;
}
__device__ __forceinline__ void ldsm4(uint32_t* r, uint32_t a) {
    asm volatile("ldmatrix.sync.aligned.m8n8.x4.shared.b16 {%0,%1,%2,%3}, [%4];"
                 : "=r"(r[0]), "=r"(r[1]), "=r"(r[2]), "=r"(r[3]) : "r"(a));
}
__device__ __forceinline__ void mma16816(float* c, const uint32_t* a,
                                         uint32_t b0, uint32_t b1) {
    asm volatile(
        "mma.sync.aligned.m16n8k16.row.col.f32.f16.f16.f32 "
        "{%0,%1,%2,%3}, {%4,%5,%6,%7}, {%8,%9}, {%0,%1,%2,%3};"
        : "+f"(c[0]), "+f"(c[1]), "+f"(c[2]), "+f"(c[3])
        : "r"(a[0]), "r"(a[1]), "r"(a[2]), "r"(a[3]), "r"(b0), "r"(b1));
}
__device__ __forceinline__ uint32_t split_pack2(float f0, float f1, uint32_t& lo_pack) {
    __half h0 = __float2half_rn(f0);
    __half h1 = __float2half_rn(f1);
    __half l0 = __float2half_rn(f0 - __half2float(h0));
    __half l1 = __float2half_rn(f1 - __half2float(h1));
    lo_pack = (uint32_t)__half_as_ushort(l0) | ((uint32_t)__half_as_ushort(l1) << 16);
    return (uint32_t)__half_as_ushort(h0) | ((uint32_t)__half_as_ushort(h1) << 16);
}

__global__ __launch_bounds__(NTHR, 2)
void varnet_hmma(const float* __restrict__ z,
                 const float* __restrict__ cnts,
                 const float* __restrict__ lams,
                 const float* __restrict__ W,
                 float* __restrict__ out,
                 int B)
{
    extern __shared__ __align__(16) char smem[];
    const uint32_t sb = smem_u32(smem);
    float* s_lam = reinterpret_cast<float*>(smem + OFF_LAM);
    float* s_c2  = reinterpret_cast<float*>(smem + OFF_C2);
    float* s_z2  = reinterpret_cast<float*>(smem + OFF_Z2);

    const int t    = threadIdx.x;
    const int wid  = t >> 5;
    const int lane = t & 31;
    const int gid  = lane >> 2;
    const int tig  = lane & 3;
    const int row0 = blockIdx.x * MT;

    // ===== staging: z (all threads, 2 batches of 8 independent LDG.128) =====
    {
        const int r  = t >> 1;
        const int h  = t & 1;
        const long long grow = (long long)row0 + r;
        const float* zr = z + grow * DZ;
        float z2p = 0.f;
        #pragma unroll
        for (int b = 0; b < 2; b++) {
            float4 v[8];
            #pragma unroll
            for (int i = 0; i < 8; i++) {
                const int j = (b * 8 + i + r + 8 * h) & 15;
                const int d = 64 * h + 4 * j;
                v[i] = (grow < B)
                    ? *reinterpret_cast<const float4*>(zr + d)
                    : make_float4(0.f, 0.f, 0.f, 0.f);
            }
            #pragma unroll
            for (int i = 0; i < 8; i++) {
                const int j = (b * 8 + i + r + 8 * h) & 15;
                const int d = 64 * h + 4 * j;
                const float4 vv = v[i];
                z2p = fmaf(vv.x, vv.x, fmaf(vv.y, vv.y,
                      fmaf(vv.z, vv.z, fmaf(vv.w, vv.w, z2p))));
                uint32_t l0, l1;
                uint32_t h0 = split_pack2(vv.x, vv.y, l0);
                uint32_t h1 = split_pack2(vv.z, vv.w, l1);
                const int byo = (r * SA + d) * 2;
                *reinterpret_cast<uint64_t*>(smem + OFF_AH + byo) =
                    (uint64_t)h0 | ((uint64_t)h1 << 32);
                *reinterpret_cast<uint64_t*>(smem + OFF_AL + byo) =
                    (uint64_t)l0 | ((uint64_t)l1 << 32);
            }
        }
        z2p += __shfl_xor_sync(0xFFFFFFFFu, z2p, 1);
        if (h == 0) s_z2[r] = z2p;
    }

    // ===== staging: 2*cnts (ALL 256 threads, 8 f4 each, one batch) =====
    {
        const int rc = t >> 2;           // center row 0..63
        const int hc = (t >> 1) & 1;     // k-half
        const int sc = t & 1;            // sub-half (chunks 0..7 / 8..15 of stagger)
        const float* cr = cnts + rc * DZ;
        float c2p = 0.f;
        float4 v[8];
        #pragma unroll
        for (int i = 0; i < 8; i++) {
            const int j = (8 * sc + i + rc + 8 * hc) & 15;
            v[i] = *reinterpret_cast<const float4*>(cr + 64 * hc + 4 * j);
        }
        #pragma unroll
        for (int i = 0; i < 8; i++) {
            const int j = (8 * sc + i + rc + 8 * hc) & 15;
            const int d = 64 * hc + 4 * j;
            const float4 vv = v[i];
            c2p = fmaf(vv.x, vv.x, fmaf(vv.y, vv.y,
                  fmaf(vv.z, vv.z, fmaf(vv.w, vv.w, c2p))));
            uint32_t l0, l1;
            uint32_t h0 = split_pack2(2.f * vv.x, 2.f * vv.y, l0);
            uint32_t h1 = split_pack2(2.f * vv.z, 2.f * vv.w, l1);
            const int byo = (rc * SB + d) * 2;
            *reinterpret_cast<uint64_t*>(smem + OFF_BH + byo) =
                (uint64_t)h0 | ((uint64_t)h1 << 32);
            *reinterpret_cast<uint64_t*>(smem + OFF_BL + byo) =
                (uint64_t)l0 | ((uint64_t)l1 << 32);
        }
        c2p += __shfl_xor_sync(0xFFFFFFFFu, c2p, 1);
        c2p += __shfl_xor_sync(0xFFFFFFFFu, c2p, 2);
        if ((t & 3) == 0) s_c2[rc] = c2p;
    }

    // ===== staging: W^2 (all threads, 4 elems) + lam =====
    {
        #pragma unroll
        for (int i = 0; i < 4; i++) {
            const int idx = t * 4 + i;         // W is [64][16] row-major, 1024 elems
            const int kc = idx >> 4, j = idx & 15;
            float w = W[idx];
            float w2 = w * w;
            __half hh = __float2half_rn(w2);
            __half hl = __float2half_rn(w2 - __half2float(hh));
            const int byo = (j * SW + kc) * 2;
            *reinterpret_cast<uint16_t*>(smem + OFF_WH + byo) = __half_as_ushort(hh);
            *reinterpret_cast<uint16_t*>(smem + OFF_WL + byo) = __half_as_ushort(hl);
        }
        if (t < K) s_lam[t] = lams[t];
    }
    __syncthreads();

    // ===== GEMM1: dot[128x64] = z.(2c)^T, pipelined ldsm/HMMA =====
    float acc[8][4];
    #pragma unroll
    for (int nt = 0; nt < 8; nt++)
        #pragma unroll
        for (int q = 0; q < 4; q++) acc[nt][q] = 0.f;

    const uint32_t aA = sb + OFF_AH +
        (uint32_t)(((16 * wid + (lane & 15)) * SA + 8 * ((lane >> 4) & 1)) * 2);
    const uint32_t aAl = aA + (OFF_AL - OFF_AH);
    const uint32_t laneB =
        (uint32_t)((((lane & 7) + 8 * ((lane >> 4) & 1)) * SB + 8 * ((lane >> 3) & 1)) * 2);
    const uint32_t aB  = sb + OFF_BH + laneB;
    const uint32_t aBl = sb + OFF_BL + laneB;
    constexpr uint32_t BP = (uint32_t)(16 * SB * 2);   // n-tile-pair stride

    {
        uint32_t ah[2][4], al[2][4], bh[2][4], bl[2][4];
        ldsm4(ah[0], aA);
        ldsm4(al[0], aAl);
        ldsm4(bh[0], aB);
        ldsm4(bl[0], aBl);

        #pragma unroll
        for (int it = 0; it < 32; it++) {
            const int s  = it >> 2;
            const int p  = it & 3;
            const int sa = s & 1;
            const int bb = it & 1;
            if (it + 1 < 32) {
                const int ns = (it + 1) >> 2;
                const int np = (it + 1) & 3;
                const uint32_t nks = (uint32_t)(32 * ns);
                if (np == 0) {
                    ldsm4(ah[ns & 1], aA  + nks);
                    ldsm4(al[ns & 1], aAl + nks);
                }
                ldsm4(bh[1 - bb], aB  + (uint32_t)np * BP + nks);
                ldsm4(bl[1 - bb], aBl + (uint32_t)np * BP + nks);
            }
            float* c0 = acc[2 * p];
            float* c1 = acc[2 * p + 1];
            mma16816(c0, ah[sa], bh[bb][0], bh[bb][1]);
            mma16816(c0, ah[sa], bl[bb][0], bl[bb][1]);
            mma16816(c0, al[sa], bh[bb][0], bh[bb][1]);
            mma16816(c1, ah[sa], bh[bb][2], bh[bb][3]);
            mma16816(c1, ah[sa], bl[bb][2], bl[bb][3]);
            mma16816(c1, al[sa], bh[bb][2], bh[bb][3]);
        }
    }

    // ===== epilogue 1: V = exp(-lam*(z2+c2-dot)) (regs), store f16 hi =====
    uint32_t vpack[8][2];
    {
        const int rA0 = 16 * wid + gid;
        const float z20 = s_z2[rA0];
        const float z21 = s_z2[rA0 + 8];
        #pragma unroll
        for (int nt = 0; nt < 8; nt++) {
            const int n0 = nt * 8 + tig * 2;
            const float c20 = s_c2[n0], c21 = s_c2[n0 + 1];
            const float lm0 = s_lam[n0], lm1 = s_lam[n0 + 1];
            float v00 = __expf(-lm0 * (z20 + c20 - acc[nt][0]));
            float v01 = __expf(-lm1 * (z20 + c21 - acc[nt][1]));
            float v10 = __expf(-lm0 * (z21 + c20 - acc[nt][2]));
            float v11 = __expf(-lm1 * (z21 + c21 - acc[nt][3]));
            __half a0 = __float2half_rn(v00), a1 = __float2half_rn(v01);
            __half b0 = __float2half_rn(v10), b1 = __float2half_rn(v11);
            vpack[nt][0] = (uint32_t)__half_as_ushort(a0) |
                           ((uint32_t)__half_as_ushort(a1) << 16);
            vpack[nt][1] = (uint32_t)__half_as_ushort(b0) |
                           ((uint32_t)__half_as_ushort(b1) << 16);
        }
    }
    __syncthreads();   // all GEMM1 reads of A region done before V overlay
    {
        const int rA0 = 16 * wid + gid;
        #pragma unroll
        for (int nt = 0; nt < 8; nt++) {
            const int n0 = nt * 8 + tig * 2;
            *reinterpret_cast<uint32_t*>(smem + OFF_VH + (rA0 * SV + n0) * 2)       = vpack[nt][0];
            *reinterpret_cast<uint32_t*>(smem + OFF_VH + ((rA0 + 8) * SV + n0) * 2) = vpack[nt][1];
        }
    }
    __syncwarp();      // V rows are warp-private

    // ===== GEMM2: beta[128x16] = Vh @ (W2h + W2l), loads hoisted =====
    float acc2[2][4];
    #pragma unroll
    for (int nt = 0; nt < 2; nt++)
        #pragma unroll
        for (int q = 0; q < 4; q++) acc2[nt][q] = 0.f;
    {
        const uint32_t aV = sb + OFF_VH +
            (uint32_t)(((16 * wid + (lane & 15)) * SV + 8 * ((lane >> 4) & 1)) * 2);
        const uint32_t laneW =
            (uint32_t)((((lane & 7) + 8 * ((lane >> 4) & 1)) * SW + 8 * ((lane >> 3) & 1)) * 2);
        const uint32_t aW  = sb + OFF_WH + laneW;
        const uint32_t aWl = sb + OFF_WL + laneW;

        uint32_t vh[4][4], wh[4][4], wl[4][4];
        #pragma unroll
        for (int s = 0; s < 4; s++) {
            const uint32_t ks = (uint32_t)(32 * s);
            ldsm4(vh[s], aV  + ks);
            ldsm4(wh[s], aW  + ks);
            ldsm4(wl[s], aWl + ks);
        }
        #pragma unroll
        for (int s = 0; s < 4; s++) {
            mma16816(acc2[0], vh[s], wh[s][0], wh[s][1]);
            mma16816(acc2[0], vh[s], wl[s][0], wl[s][1]);
            mma16816(acc2[1], vh[s], wh[s][2], wh[s][3]);
            mma16816(acc2[1], vh[s], wl[s][2], wl[s][3]);
        }
    }

    // ===== epilogue 2: sigma = rsqrt(beta+eps), store =====
    {
        const int r0 = 16 * wid + gid;
        const long long g0 = (long long)row0 + r0;
        const long long g1 = g0 + 8;
        #pragma unroll
        for (int nt = 0; nt < 2; nt++) {
            const int j0 = nt * 8 + tig * 2;
            if (g0 < B) {
                float2 o = make_float2(rsqrtf(acc2[nt][0] + EPS),
                                       rsqrtf(acc2[nt][1] + EPS));
                *reinterpret_cast<float2*>(out + g0 * OUTD + j0) = o;
            }
            if (g1 < B) {
                float2 o = make_float2(rsqrtf(acc2[nt][2] + EPS),
                                       rsqrtf(acc2[nt][3] + EPS));
                *reinterpret_cast<float2*>(out + g1 * OUTD + j0) = o;
            }
        }
    }
}

extern "C" void kernel_launch(void* const* d_in, const int* in_sizes, int n_in,
                              void* d_out, int out_size)
{
    const float* z    = (const float*)d_in[0];
    const float* cnts = (const float*)d_in[1];
    const float* lams = (const float*)d_in[2];
    const float* W    = (const float*)d_in[3];
    float* out = (float*)d_out;

    const int B = in_sizes[0] / DZ;
    cudaFuncSetAttribute(varnet_hmma,
                         cudaFuncAttributeMaxDynamicSharedMemorySize, SMEM_BYTES);
    const int grid = (B + MT - 1) / MT;
    varnet_hmma<<<grid, NTHR, SMEM_BYTES>>>(z, cnts, lams, W, out, B);
}

// round 12
// speedup vs baseline: 1.5711x; 1.4781x over previous
#include <cuda_runtime.h>
#include <cuda_fp16.h>
#include <cstdint>

// sigma = rsqrt( exp(-||z-c_k||^2 * lam_k) @ (W*W) + eps )
// B=262144, K=64, DZ=128, OUT=16.
// f16-split mma.sync + ldmatrix; K-dim two-pass staging -> 59.5KB smem,
// __launch_bounds__(256,3) -> 3 CTAs/SM (24 warps) for latency hiding.

constexpr int K    = 64;
constexpr int DZ   = 128;
constexpr int OUTD = 16;
constexpr int MT   = 128;
constexpr int NTHR = 256;
constexpr float EPS = 1e-6f;

constexpr int SA = 72;   // f16 stride per 64-col pass (36 words = 4 mod 8)
constexpr int SB = 72;
constexpr int SV = 72;
constexpr int SW = 72;

constexpr int OFF_AH  = 0;                        // [128][72] f16
constexpr int OFF_AL  = OFF_AH + MT * SA * 2;     // 18432
constexpr int OFF_BH  = OFF_AL + MT * SA * 2;     // 36864 [64][72]
constexpr int OFF_BL  = OFF_BH + K * SB * 2;      // 46080
constexpr int OFF_WH  = OFF_BL + K * SB * 2;      // 55296 [16][72]
constexpr int OFF_WL  = OFF_WH + OUTD * SW * 2;   // 57600
constexpr int OFF_LAM = OFF_WL + OUTD * SW * 2;   // 59904
constexpr int OFF_C2  = OFF_LAM + 256;
constexpr int OFF_Z2  = OFF_C2 + 256;
constexpr int SMEM_BYTES = OFF_Z2 + 512;          // 60928
constexpr int OFF_VH  = OFF_AH;                   // V overlays A after GEMM1

__device__ __forceinline__ uint32_t smem_u32(const void* p) {
    uint32_t a;
    asm("{ .reg .u64 t; cvta.to.shared.u64 t, %1; cvt.u32.u64 %0, t; }" : "=r"(a) : "l"(p));
    return a;
}
__device__ __forceinline__ void ldsm4(uint32_t* r, uint32_t a) {
    asm volatile("ldmatrix.sync.aligned.m8n8.x4.shared.b16 {%0,%1,%2,%3}, [%4];"
                 : "=r"(r[0]), "=r"(r[1]), "=r"(r[2]), "=r"(r[3]) : "r"(a));
}
__device__ __forceinline__ void mma16816(float* c, const uint32_t* a,
                                         uint32_t b0, uint32_t b1) {
    asm volatile(
        "mma.sync.aligned.m16n8k16.row.col.f32.f16.f16.f32 "
        "{%0,%1,%2,%3}, {%4,%5,%6,%7}, {%8,%9}, {%0,%1,%2,%3};"
        : "+f"(c[0]), "+f"(c[1]), "+f"(c[2]), "+f"(c[3])
        : "r"(a[0]), "r"(a[1]), "r"(a[2]), "r"(a[3]), "r"(b0), "r"(b1));
}
__device__ __forceinline__ uint32_t split_pack2(float f0, float f1, uint32_t& lo_pack) {
    __half h0 = __float2half_rn(f0);
    __half h1 = __float2half_rn(f1);
    __half l0 = __float2half_rn(f0 - __half2float(h0));
    __half l1 = __float2half_rn(f1 - __half2float(h1));
    lo_pack = (uint32_t)__half_as_ushort(l0) | ((uint32_t)__half_as_ushort(l1) << 16);
    return (uint32_t)__half_as_ushort(h0) | ((uint32_t)__half_as_ushort(h1) << 16);
}

__global__ __launch_bounds__(NTHR, 3)
void varnet_hmma(const float* __restrict__ z,
                 const float* __restrict__ cnts,
                 const float* __restrict__ lams,
                 const float* __restrict__ W,
                 float* __restrict__ out,
                 int B)
{
    extern __shared__ __align__(16) char smem[];
    const uint32_t sb = smem_u32(smem);
    float* s_lam = reinterpret_cast<float*>(smem + OFF_LAM);
    float* s_c2  = reinterpret_cast<float*>(smem + OFF_C2);
    float* s_z2  = reinterpret_cast<float*>(smem + OFF_Z2);

    const int t    = threadIdx.x;
    const int wid  = t >> 5;
    const int lane = t & 31;
    const int gid  = lane >> 2;
    const int tig  = lane & 3;
    const int row0 = blockIdx.x * MT;

    // staging roles
    const int zr_  = t >> 1;          // z row 0..127
    const int zh_  = t & 1;           // 32-col half within the pass
    const int cr_  = t >> 2;          // cnts row 0..63
    const int cq_  = t & 3;           // 16-col quarter within the pass

    const long long zrow = (long long)row0 + zr_;
    const float* zptr = z + zrow * DZ;
    const float* cptr = cnts + cr_ * DZ;

    float z2acc = 0.f, c2acc = 0.f;

    // GEMM state
    float acc[8][4];
    #pragma unroll
    for (int nt = 0; nt < 8; nt++)
        #pragma unroll
        for (int q = 0; q < 4; q++) acc[nt][q] = 0.f;

    const uint32_t aA = sb + OFF_AH +
        (uint32_t)(((16 * wid + (lane & 15)) * SA + 8 * ((lane >> 4) & 1)) * 2);
    const uint32_t aAl = aA + (OFF_AL - OFF_AH);
    const uint32_t laneB =
        (uint32_t)((((lane & 7) + 8 * ((lane >> 4) & 1)) * SB + 8 * ((lane >> 3) & 1)) * 2);
    const uint32_t aB  = sb + OFF_BH + laneB;
    const uint32_t aBl = sb + OFF_BL + laneB;
    constexpr uint32_t BP = (uint32_t)(16 * SB * 2);   // n-tile-pair stride

    #pragma unroll
    for (int pass = 0; pass < 2; pass++) {
        const int kb = 64 * pass;

        if (pass == 1) __syncthreads();   // GEMM pass-0 reads done before restage

        // ---- stage z: 8 f4 per thread, 2 batches of 4 (MLP=4) ----
        #pragma unroll
        for (int b = 0; b < 2; b++) {
            float4 v[4];
            #pragma unroll
            for (int i = 0; i < 4; i++) {
                const int j = (b * 4 + i + zr_) & 7;
                const int d = kb + 32 * zh_ + 4 * j;
                v[i] = (zrow < B)
                    ? *reinterpret_cast<const float4*>(zptr + d)
                    : make_float4(0.f, 0.f, 0.f, 0.f);
            }
            #pragma unroll
            for (int i = 0; i < 4; i++) {
                const int j = (b * 4 + i + zr_) & 7;
                const float4 vv = v[i];
                z2acc = fmaf(vv.x, vv.x, fmaf(vv.y, vv.y,
                        fmaf(vv.z, vv.z, fmaf(vv.w, vv.w, z2acc))));
                uint32_t l0, l1;
                uint32_t h0 = split_pack2(vv.x, vv.y, l0);
                uint32_t h1 = split_pack2(vv.z, vv.w, l1);
                const int byo = (zr_ * SA + 32 * zh_ + 4 * j) * 2;
                *reinterpret_cast<uint64_t*>(smem + OFF_AH + byo) =
                    (uint64_t)h0 | ((uint64_t)h1 << 32);
                *reinterpret_cast<uint64_t*>(smem + OFF_AL + byo) =
                    (uint64_t)l0 | ((uint64_t)l1 << 32);
            }
        }

        // ---- stage 2*cnts: 4 f4 per thread, one batch (MLP=4) ----
        {
            float4 v[4];
            #pragma unroll
            for (int i = 0; i < 4; i++) {
                const int j = (i + cr_) & 3;
                v[i] = *reinterpret_cast<const float4*>(cptr + kb + 16 * cq_ + 4 * j);
            }
            #pragma unroll
            for (int i = 0; i < 4; i++) {
                const int j = (i + cr_) & 3;
                const float4 vv = v[i];
                c2acc = fmaf(vv.x, vv.x, fmaf(vv.y, vv.y,
                        fmaf(vv.z, vv.z, fmaf(vv.w, vv.w, c2acc))));
                uint32_t l0, l1;
                uint32_t h0 = split_pack2(2.f * vv.x, 2.f * vv.y, l0);
                uint32_t h1 = split_pack2(2.f * vv.z, 2.f * vv.w, l1);
                const int byo = (cr_ * SB + 16 * cq_ + 4 * j) * 2;
                *reinterpret_cast<uint64_t*>(smem + OFF_BH + byo) =
                    (uint64_t)h0 | ((uint64_t)h1 << 32);
                *reinterpret_cast<uint64_t*>(smem + OFF_BL + byo) =
                    (uint64_t)l0 | ((uint64_t)l1 << 32);
            }
        }

        // ---- pass-0 only: W^2 + lam; pass-1: finalize z2/c2 ----
        if (pass == 0) {
            #pragma unroll
            for (int i = 0; i < 4; i++) {
                const int idx = t * 4 + i;     // W [64][16] row-major
                const int kc = idx >> 4, j = idx & 15;
                float w = W[idx];
                float w2 = w * w;
                __half hh = __float2half_rn(w2);
                __half hl = __float2half_rn(w2 - __half2float(hh));
                const int byo = (j * SW + kc) * 2;
                *reinterpret_cast<uint16_t*>(smem + OFF_WH + byo) = __half_as_ushort(hh);
                *reinterpret_cast<uint16_t*>(smem + OFF_WL + byo) = __half_as_ushort(hl);
            }
            if (t < K) s_lam[t] = lams[t];
        } else {
            float zs = z2acc + __shfl_xor_sync(0xFFFFFFFFu, z2acc, 1);
            if (zh_ == 0) s_z2[zr_] = zs;
            float cs = c2acc;
            cs += __shfl_xor_sync(0xFFFFFFFFu, cs, 1);
            cs += __shfl_xor_sync(0xFFFFFFFFu, cs, 2);
            if (cq_ == 0) s_c2[cr_] = cs;
        }
        __syncthreads();

        // ---- GEMM pass: 4 k-steps over this 64-col chunk ----
        #pragma unroll
        for (int s = 0; s < 4; s++) {
            const uint32_t ks = (uint32_t)(32 * s);
            uint32_t ah[4], al[4];
            ldsm4(ah, aA  + ks);
            ldsm4(al, aAl + ks);
            #pragma unroll
            for (int p = 0; p < 4; p++) {
                uint32_t bh[4], bl[4];
                ldsm4(bh, aB  + (uint32_t)p * BP + ks);
                ldsm4(bl, aBl + (uint32_t)p * BP + ks);
                float* c0 = acc[2 * p];
                float* c1 = acc[2 * p + 1];
                mma16816(c0, ah, bh[0], bh[1]);
                mma16816(c0, ah, bl[0], bl[1]);
                mma16816(c0, al, bh[0], bh[1]);
                mma16816(c1, ah, bh[2], bh[3]);
                mma16816(c1, ah, bl[2], bl[3]);
                mma16816(c1, al, bh[2], bh[3]);
            }
        }
    }

    // ===== epilogue 1: V = exp(-lam*(z2+c2-dot)) (regs), store f16 hi =====
    uint32_t vpack[8][2];
    {
        const int rA0 = 16 * wid + gid;
        const float z20 = s_z2[rA0];
        const float z21 = s_z2[rA0 + 8];
        #pragma unroll
        for (int nt = 0; nt < 8; nt++) {
            const int n0 = nt * 8 + tig * 2;
            const float c20 = s_c2[n0], c21 = s_c2[n0 + 1];
            const float lm0 = s_lam[n0], lm1 = s_lam[n0 + 1];
            float v00 = __expf(-lm0 * (z20 + c20 - acc[nt][0]));
            float v01 = __expf(-lm1 * (z20 + c21 - acc[nt][1]));
            float v10 = __expf(-lm0 * (z21 + c20 - acc[nt][2]));
            float v11 = __expf(-lm1 * (z21 + c21 - acc[nt][3]));
            __half a0 = __float2half_rn(v00), a1 = __float2half_rn(v01);
            __half b0 = __float2half_rn(v10), b1 = __float2half_rn(v11);
            vpack[nt][0] = (uint32_t)__half_as_ushort(a0) |
                           ((uint32_t)__half_as_ushort(a1) << 16);
            vpack[nt][1] = (uint32_t)__half_as_ushort(b0) |
                           ((uint32_t)__half_as_ushort(b1) << 16);
        }
    }
    __syncthreads();   // GEMM pass-1 reads of A region done before V overlay
    {
        const int rA0 = 16 * wid + gid;
        #pragma unroll
        for (int nt = 0; nt < 8; nt++) {
            const int n0 = nt * 8 + tig * 2;
            *reinterpret_cast<uint32_t*>(smem + OFF_VH + (rA0 * SV + n0) * 2)       = vpack[nt][0];
            *reinterpret_cast<uint32_t*>(smem + OFF_VH + ((rA0 + 8) * SV + n0) * 2) = vpack[nt][1];
        }
    }
    __syncwarp();      // V rows are warp-private

    // ===== GEMM2: beta[128x16] = Vh @ (W2h + W2l), K=64 =====
    float acc2[2][4];
    #pragma unroll
    for (int nt = 0; nt < 2; nt++)
        #pragma unroll
        for (int q = 0; q < 4; q++) acc2[nt][q] = 0.f;
    {
        const uint32_t aV = sb + OFF_VH +
            (uint32_t)(((16 * wid + (lane & 15)) * SV + 8 * ((lane >> 4) & 1)) * 2);
        const uint32_t laneW =
            (uint32_t)((((lane & 7) + 8 * ((lane >> 4) & 1)) * SW + 8 * ((lane >> 3) & 1)) * 2);
        const uint32_t aW  = sb + OFF_WH + laneW;
        const uint32_t aWl = sb + OFF_WL + laneW;

        #pragma unroll
        for (int s = 0; s < 4; s++) {
            const uint32_t ks = (uint32_t)(32 * s);
            uint32_t vh[4], wh[4], wl[4];
            ldsm4(vh, aV  + ks);
            ldsm4(wh, aW  + ks);
            ldsm4(wl, aWl + ks);
            mma16816(acc2[0], vh, wh[0], wh[1]);
            mma16816(acc2[0], vh, wl[0], wl[1]);
            mma16816(acc2[1], vh, wh[2], wh[3]);
            mma16816(acc2[1], vh, wl[2], wl[3]);
        }
    }

    // ===== epilogue 2: sigma = rsqrt(beta+eps), store =====
    {
        const int r0 = 16 * wid + gid;
        const long long g0 = (long long)row0 + r0;
        const long long g1 = g0 + 8;
        #pragma unroll
        for (int nt = 0; nt < 2; nt++) {
            const int j0 = nt * 8 + tig * 2;
            if (g0 < B) {
                float2 o = make_float2(rsqrtf(acc2[nt][0] + EPS),
                                       rsqrtf(acc2[nt][1] + EPS));
                *reinterpret_cast<float2*>(out + g0 * OUTD + j0) = o;
            }
            if (g1 < B) {
                float2 o = make_float2(rsqrtf(acc2[nt][2] + EPS),
                                       rsqrtf(acc2[nt][3] + EPS));
                *reinterpret_cast<float2*>(out + g1 * OUTD + j0) = o;
            }
        }
    }
}

extern "C" void kernel_launch(void* const* d_in, const int* in_sizes, int n_in,
                              void* d_out, int out_size)
{
    const float* z    = (const float*)d_in[0];
    const float* cnts = (const float*)d_in[1];
    const float* lams = (const float*)d_in[2];
    const float* W    = (const float*)d_in[3];
    float* out = (float*)d_out;

    const int B = in_sizes[0] / DZ;
    cudaFuncSetAttribute(varnet_hmma,
                         cudaFuncAttributeMaxDynamicSharedMemorySize, SMEM_BYTES);
    const int grid = (B + MT - 1) / MT;
    varnet_hmma<<<grid, NTHR, SMEM_BYTES>>>(z, cnts, lams, W, out, B);
}

// round 13
// speedup vs baseline: 1.6443x; 1.0466x over previous
#include <cuda_runtime.h>
#include <cuda_fp16.h>
#include <cstdint>

// sigma = rsqrt( exp(-||z-c_k||^2 * lam_k) @ (W*W) + eps )
// B=262144, K=64, DZ=128, OUT=16.
// f16-split mma.sync + ldmatrix; two-pass K staging (59.5KB smem, 3 CTAs/SM);
// GEMM2 consumes V directly from GEMM1 accumulator registers (fragment
// layout identity) -- no V smem round trip, no extra barriers.

constexpr int K    = 64;
constexpr int DZ   = 128;
constexpr int OUTD = 16;
constexpr int MT   = 128;
constexpr int NTHR = 256;
constexpr float EPS = 1e-6f;

constexpr int SA = 72;   // f16 stride per 64-col pass (36 words = 4 mod 8)
constexpr int SB = 72;
constexpr int SW = 72;

constexpr int OFF_AH  = 0;                        // [128][72] f16
constexpr int OFF_AL  = OFF_AH + MT * SA * 2;     // 18432
constexpr int OFF_BH  = OFF_AL + MT * SA * 2;     // 36864 [64][72]
constexpr int OFF_BL  = OFF_BH + K * SB * 2;      // 46080
constexpr int OFF_WH  = OFF_BL + K * SB * 2;      // 55296 [16][72]
constexpr int OFF_WL  = OFF_WH + OUTD * SW * 2;   // 57600
constexpr int OFF_LAM = OFF_WL + OUTD * SW * 2;   // 59904
constexpr int OFF_C2  = OFF_LAM + 256;
constexpr int OFF_Z2  = OFF_C2 + 256;
constexpr int SMEM_BYTES = OFF_Z2 + 512;          // 60928

__device__ __forceinline__ uint32_t smem_u32(const void* p) {
    uint32_t a;
    asm("{ .reg .u64 t; cvta.to.shared.u64 t, %1; cvt.u32.u64 %0, t; }" : "=r"(a) : "l"(p));
    return a;
}
__device__ __forceinline__ void ldsm4(uint32_t* r, uint32_t a) {
    asm volatile("ldmatrix.sync.aligned.m8n8.x4.shared.b16 {%0,%1,%2,%3}, [%4];"
                 : "=r"(r[0]), "=r"(r[1]), "=r"(r[2]), "=r"(r[3]) : "r"(a));
}
__device__ __forceinline__ void mma16816(float* c, const uint32_t* a,
                                         uint32_t b0, uint32_t b1) {
    asm volatile(
        "mma.sync.aligned.m16n8k16.row.col.f32.f16.f16.f32 "
        "{%0,%1,%2,%3}, {%4,%5,%6,%7}, {%8,%9}, {%0,%1,%2,%3};"
        : "+f"(c[0]), "+f"(c[1]), "+f"(c[2]), "+f"(c[3])
        : "r"(a[0]), "r"(a[1]), "r"(a[2]), "r"(a[3]), "r"(b0), "r"(b1));
}
__device__ __forceinline__ uint32_t split_pack2(float f0, float f1, uint32_t& lo_pack) {
    __half h0 = __float2half_rn(f0);
    __half h1 = __float2half_rn(f1);
    __half l0 = __float2half_rn(f0 - __half2float(h0));
    __half l1 = __float2half_rn(f1 - __half2float(h1));
    lo_pack = (uint32_t)__half_as_ushort(l0) | ((uint32_t)__half_as_ushort(l1) << 16);
    return (uint32_t)__half_as_ushort(h0) | ((uint32_t)__half_as_ushort(h1) << 16);
}

__global__ __launch_bounds__(NTHR, 3)
void varnet_hmma(const float* __restrict__ z,
                 const float* __restrict__ cnts,
                 const float* __restrict__ lams,
                 const float* __restrict__ W,
                 float* __restrict__ out,
                 int B)
{
    extern __shared__ __align__(16) char smem[];
    const uint32_t sb = smem_u32(smem);
    float* s_lam = reinterpret_cast<float*>(smem + OFF_LAM);
    float* s_c2  = reinterpret_cast<float*>(smem + OFF_C2);
    float* s_z2  = reinterpret_cast<float*>(smem + OFF_Z2);

    const int t    = threadIdx.x;
    const int wid  = t >> 5;
    const int lane = t & 31;
    const int gid  = lane >> 2;
    const int tig  = lane & 3;
    const int row0 = blockIdx.x * MT;

    // staging roles
    const int zr_  = t >> 1;          // z row 0..127
    const int zh_  = t & 1;           // 32-col half within the pass
    const int cr_  = t >> 2;          // cnts row 0..63
    const int cq_  = t & 3;           // 16-col quarter within the pass

    const long long zrow = (long long)row0 + zr_;
    const float* zptr = z + zrow * DZ;
    const float* cptr = cnts + cr_ * DZ;

    float z2acc = 0.f, c2acc = 0.f;

    // GEMM1 accumulators
    float acc[8][4];
    #pragma unroll
    for (int nt = 0; nt < 8; nt++)
        #pragma unroll
        for (int q = 0; q < 4; q++) acc[nt][q] = 0.f;

    const uint32_t aA = sb + OFF_AH +
        (uint32_t)(((16 * wid + (lane & 15)) * SA + 8 * ((lane >> 4) & 1)) * 2);
    const uint32_t aAl = aA + (OFF_AL - OFF_AH);
    const uint32_t laneB =
        (uint32_t)((((lane & 7) + 8 * ((lane >> 4) & 1)) * SB + 8 * ((lane >> 3) & 1)) * 2);
    const uint32_t aB  = sb + OFF_BH + laneB;
    const uint32_t aBl = sb + OFF_BL + laneB;
    constexpr uint32_t BP = (uint32_t)(16 * SB * 2);   // n-tile-pair stride

    #pragma unroll
    for (int pass = 0; pass < 2; pass++) {
        const int kb = 64 * pass;

        if (pass == 1) __syncthreads();   // GEMM pass-0 reads done before restage

        // ---- stage z: 8 f4 per thread, 2 batches of 4 (MLP=4) ----
        #pragma unroll
        for (int b = 0; b < 2; b++) {
            float4 v[4];
            #pragma unroll
            for (int i = 0; i < 4; i++) {
                const int j = (b * 4 + i + zr_) & 7;
                const int d = kb + 32 * zh_ + 4 * j;
                v[i] = (zrow < B)
                    ? *reinterpret_cast<const float4*>(zptr + d)
                    : make_float4(0.f, 0.f, 0.f, 0.f);
            }
            #pragma unroll
            for (int i = 0; i < 4; i++) {
                const int j = (b * 4 + i + zr_) & 7;
                const float4 vv = v[i];
                z2acc = fmaf(vv.x, vv.x, fmaf(vv.y, vv.y,
                        fmaf(vv.z, vv.z, fmaf(vv.w, vv.w, z2acc))));
                uint32_t l0, l1;
                uint32_t h0 = split_pack2(vv.x, vv.y, l0);
                uint32_t h1 = split_pack2(vv.z, vv.w, l1);
                const int byo = (zr_ * SA + 32 * zh_ + 4 * j) * 2;
                *reinterpret_cast<uint64_t*>(smem + OFF_AH + byo) =
                    (uint64_t)h0 | ((uint64_t)h1 << 32);
                *reinterpret_cast<uint64_t*>(smem + OFF_AL + byo) =
                    (uint64_t)l0 | ((uint64_t)l1 << 32);
            }
        }

        // ---- stage 2*cnts: 4 f4 per thread, one batch (MLP=4) ----
        {
            float4 v[4];
            #pragma unroll
            for (int i = 0; i < 4; i++) {
                const int j = (i + cr_) & 3;
                v[i] = *reinterpret_cast<const float4*>(cptr + kb + 16 * cq_ + 4 * j);
            }
            #pragma unroll
            for (int i = 0; i < 4; i++) {
                const int j = (i + cr_) & 3;
                const float4 vv = v[i];
                c2acc = fmaf(vv.x, vv.x, fmaf(vv.y, vv.y,
                        fmaf(vv.z, vv.z, fmaf(vv.w, vv.w, c2acc))));
                uint32_t l0, l1;
                uint32_t h0 = split_pack2(2.f * vv.x, 2.f * vv.y, l0);
                uint32_t h1 = split_pack2(2.f * vv.z, 2.f * vv.w, l1);
                const int byo = (cr_ * SB + 16 * cq_ + 4 * j) * 2;
                *reinterpret_cast<uint64_t*>(smem + OFF_BH + byo) =
                    (uint64_t)h0 | ((uint64_t)h1 << 32);
                *reinterpret_cast<uint64_t*>(smem + OFF_BL + byo) =
                    (uint64_t)l0 | ((uint64_t)l1 << 32);
            }
        }

        // ---- pass-0 only: W^2 + lam; pass-1: finalize z2/c2 ----
        if (pass == 0) {
            #pragma unroll
            for (int i = 0; i < 4; i++) {
                const int idx = t * 4 + i;     // W [64][16] row-major
                const int kc = idx >> 4, j = idx & 15;
                float w = W[idx];
                float w2 = w * w;
                __half hh = __float2half_rn(w2);
                __half hl = __float2half_rn(w2 - __half2float(hh));
                const int byo = (j * SW + kc) * 2;
                *reinterpret_cast<uint16_t*>(smem + OFF_WH + byo) = __half_as_ushort(hh);
                *reinterpret_cast<uint16_t*>(smem + OFF_WL + byo) = __half_as_ushort(hl);
            }
            if (t < K) s_lam[t] = lams[t];
        } else {
            float zs = z2acc + __shfl_xor_sync(0xFFFFFFFFu, z2acc, 1);
            if (zh_ == 0) s_z2[zr_] = zs;
            float cs = c2acc;
            cs += __shfl_xor_sync(0xFFFFFFFFu, cs, 1);
            cs += __shfl_xor_sync(0xFFFFFFFFu, cs, 2);
            if (cq_ == 0) s_c2[cr_] = cs;
        }
        __syncthreads();

        // ---- GEMM pass: 4 k-steps over this 64-col chunk ----
        #pragma unroll
        for (int s = 0; s < 4; s++) {
            const uint32_t ks = (uint32_t)(32 * s);
            uint32_t ah[4], al[4];
            ldsm4(ah, aA  + ks);
            ldsm4(al, aAl + ks);
            #pragma unroll
            for (int p = 0; p < 4; p++) {
                uint32_t bh[4], bl[4];
                ldsm4(bh, aB  + (uint32_t)p * BP + ks);
                ldsm4(bl, aBl + (uint32_t)p * BP + ks);
                float* c0 = acc[2 * p];
                float* c1 = acc[2 * p + 1];
                mma16816(c0, ah, bh[0], bh[1]);
                mma16816(c0, ah, bl[0], bl[1]);
                mma16816(c0, al, bh[0], bh[1]);
                mma16816(c1, ah, bh[2], bh[3]);
                mma16816(c1, ah, bl[2], bl[3]);
                mma16816(c1, al, bh[2], bh[3]);
            }
        }
    }

    // ===== epilogue 1: V = exp(-lam*(z2+c2-dot)), pack to f16x2 registers.
    // vpack[nt][0] = rows gid   @ cols {nt*8+2tig, +1} (low f16 = even col)
    // vpack[nt][1] = rows gid+8 -- exactly the m16n8k16 A-fragment pieces
    // for GEMM2 (k = center axis), so NO smem round trip is needed.
    uint32_t vpack[8][2];
    {
        const int rA0 = 16 * wid + gid;
        const float z20 = s_z2[rA0];
        const float z21 = s_z2[rA0 + 8];
        #pragma unroll
        for (int nt = 0; nt < 8; nt++) {
            const int n0 = nt * 8 + tig * 2;
            const float c20 = s_c2[n0], c21 = s_c2[n0 + 1];
            const float lm0 = s_lam[n0], lm1 = s_lam[n0 + 1];
            float v00 = __expf(-lm0 * (z20 + c20 - acc[nt][0]));
            float v01 = __expf(-lm1 * (z20 + c21 - acc[nt][1]));
            float v10 = __expf(-lm0 * (z21 + c20 - acc[nt][2]));
            float v11 = __expf(-lm1 * (z21 + c21 - acc[nt][3]));
            __half a0 = __float2half_rn(v00), a1 = __float2half_rn(v01);
            __half b0 = __float2half_rn(v10), b1 = __float2half_rn(v11);
            vpack[nt][0] = (uint32_t)__half_as_ushort(a0) |
                           ((uint32_t)__half_as_ushort(a1) << 16);
            vpack[nt][1] = (uint32_t)__half_as_ushort(b0) |
                           ((uint32_t)__half_as_ushort(b1) << 16);
        }
    }

    // ===== GEMM2: beta[128x16] = Vh @ (W2h + W2l), V from registers =====
    float acc2[2][4];
    #pragma unroll
    for (int nt = 0; nt < 2; nt++)
        #pragma unroll
        for (int q = 0; q < 4; q++) acc2[nt][q] = 0.f;
    {
        const uint32_t laneW =
            (uint32_t)((((lane & 7) + 8 * ((lane >> 4) & 1)) * SW + 8 * ((lane >> 3) & 1)) * 2);
        const uint32_t aW  = sb + OFF_WH + laneW;
        const uint32_t aWl = sb + OFF_WL + laneW;

        #pragma unroll
        for (int s = 0; s < 4; s++) {
            const uint32_t ks = (uint32_t)(32 * s);
            uint32_t av[4] = { vpack[2 * s][0], vpack[2 * s][1],
                               vpack[2 * s + 1][0], vpack[2 * s + 1][1] };
            uint32_t wh[4], wl[4];
            ldsm4(wh, aW  + ks);
            ldsm4(wl, aWl + ks);
            mma16816(acc2[0], av, wh[0], wh[1]);
            mma16816(acc2[0], av, wl[0], wl[1]);
            mma16816(acc2[1], av, wh[2], wh[3]);
            mma16816(acc2[1], av, wl[2], wl[3]);
        }
    }

    // ===== epilogue 2: sigma = rsqrt(beta+eps), store =====
    {
        const int r0 = 16 * wid + gid;
        const long long g0 = (long long)row0 + r0;
        const long long g1 = g0 + 8;
        #pragma unroll
        for (int nt = 0; nt < 2; nt++) {
            const int j0 = nt * 8 + tig * 2;
            if (g0 < B) {
                float2 o = make_float2(rsqrtf(acc2[nt][0] + EPS),
                                       rsqrtf(acc2[nt][1] + EPS));
                *reinterpret_cast<float2*>(out + g0 * OUTD + j0) = o;
            }
            if (g1 < B) {
                float2 o = make_float2(rsqrtf(acc2[nt][2] + EPS),
                                       rsqrtf(acc2[nt][3] + EPS));
                *reinterpret_cast<float2*>(out + g1 * OUTD + j0) = o;
            }
        }
    }
}

extern "C" void kernel_launch(void* const* d_in, const int* in_sizes, int n_in,
                              void* d_out, int out_size)
{
    const float* z    = (const float*)d_in[0];
    const float* cnts = (const float*)d_in[1];
    const float* lams = (const float*)d_in[2];
    const float* W    = (const float*)d_in[3];
    float* out = (float*)d_out;

    const int B = in_sizes[0] / DZ;
    cudaFuncSetAttribute(varnet_hmma,
                         cudaFuncAttributeMaxDynamicSharedMemorySize, SMEM_BYTES);
    const int grid = (B + MT - 1) / MT;
    varnet_hmma<<<grid, NTHR, SMEM_BYTES>>>(z, cnts, lams, W, out, B);
}